// round 9
// baseline (speedup 1.0000x reference)
#include <cuda_runtime.h>
#include <stdint.h>

#define EPS 1e-10f
#define BLOCK 256
#define SEGS 4
#define MAX_B 4096

// Per-row best, packed: high 32 = order-preserving key bits, low 32 = ~idx
// (so at equal key, LOWER index wins the max — matches jnp.argmax).
__device__ unsigned long long g_best[MAX_B];
// 1 if big0 is logits (contains negatives), 0 if big0 is exp_noise (>=0).
__device__ int g_big0_is_logits;

__device__ __forceinline__ unsigned int order_f32(float f)
{
    unsigned int u = __float_as_uint(f);
    unsigned int m = ((int)u >> 31) | 0x80000000u;  // neg: all-ones; pos: sign bit
    return u ^ m;                                    // monotone float -> uint
}

// Zero the scratch and detect which big tensor is logits. Deterministic.
__global__ void init_kernel(const float* __restrict__ big0, int B, int n)
{
    __shared__ int has_neg;
    if (threadIdx.x == 0) has_neg = 0;
    __syncthreads();
    for (int i = threadIdx.x; i < B; i += blockDim.x)
        g_best[i] = 0ull;
    for (int i = threadIdx.x; i < n; i += blockDim.x)
        if (big0[i] < 0.0f) has_neg = 1;   // benign race: all writers write 1
    __syncthreads();
    if (threadIdx.x == 0) g_big0_is_logits = has_neg;
}

// SEGS CTAs per row; each streams a contiguous quarter of the row and
// combines via one atomicMax on the packed (key, ~idx).
// Sampled key = l/t - log(n + EPS)  ==  argmax of softmax(l/t)/(n + EPS).
__global__ __launch_bounds__(BLOCK) void draft_sampler_kernel(
    const float* __restrict__ big0,
    const float* __restrict__ big1,
    const float* __restrict__ temps,
    int B, int V)
{
    const float* __restrict__ logits = g_big0_is_logits ? big0 : big1;
    const float* __restrict__ noise  = g_big0_is_logits ? big1 : big0;

    const int row = blockIdx.x % B;
    const int seg = blockIdx.x / B;

    const float t = temps[row];
    const bool greedy = (t == 0.0f);
    const float inv_t = greedy ? 1.0f : (1.0f / t);

    const int nvec = V >> 2;                       // V % 4 == 0
    const int segLen = nvec / SEGS;
    const int lo = seg * segLen;
    const int hi = (seg == SEGS - 1) ? nvec : lo + segLen;

    const float4* __restrict__ l4 =
        reinterpret_cast<const float4*>(logits + (long long)row * V);
    const float4* __restrict__ n4 =
        reinterpret_cast<const float4*>(noise + (long long)row * V);

    float bestKey = -3.402823466e38f;
    int   bestIdx = 0;

    if (greedy) {
        for (int i = lo + threadIdx.x; i < hi; i += BLOCK) {
            const float4 lv = l4[i];
            const int base = i << 2;
            if (lv.x > bestKey) { bestKey = lv.x; bestIdx = base;     }
            if (lv.y > bestKey) { bestKey = lv.y; bestIdx = base + 1; }
            if (lv.z > bestKey) { bestKey = lv.z; bestIdx = base + 2; }
            if (lv.w > bestKey) { bestKey = lv.w; bestIdx = base + 3; }
        }
    } else {
        for (int i = lo + threadIdx.x; i < hi; i += BLOCK) {
            const float4 lv = l4[i];
            const float4 nv = n4[i];
            const float k0 = lv.x * inv_t - __logf(nv.x + EPS);
            const float k1 = lv.y * inv_t - __logf(nv.y + EPS);
            const float k2 = lv.z * inv_t - __logf(nv.z + EPS);
            const float k3 = lv.w * inv_t - __logf(nv.w + EPS);
            const int base = i << 2;
            if (k0 > bestKey) { bestKey = k0; bestIdx = base;     }
            if (k1 > bestKey) { bestKey = k1; bestIdx = base + 1; }
            if (k2 > bestKey) { bestKey = k2; bestIdx = base + 2; }
            if (k3 > bestKey) { bestKey = k3; bestIdx = base + 3; }
        }
    }

    // Pack and reduce as u64 max (tie-break folded into ~idx).
    unsigned long long best =
        ((unsigned long long)order_f32(bestKey) << 32) | (unsigned int)(~bestIdx);

    #pragma unroll
    for (int off = 16; off > 0; off >>= 1) {
        unsigned long long o = __shfl_down_sync(0xFFFFFFFFu, best, off);
        if (o > best) best = o;
    }

    __shared__ unsigned long long sbest[BLOCK / 32];
    const int wid = threadIdx.x >> 5;
    const int lid = threadIdx.x & 31;
    if (lid == 0) sbest[wid] = best;
    __syncthreads();

    if (wid == 0) {
        constexpr int NW = BLOCK / 32;  // 8
        best = (lid < NW) ? sbest[lid] : 0ull;
        #pragma unroll
        for (int off = 4; off > 0; off >>= 1) {
            unsigned long long o = __shfl_down_sync(0xFFFFFFFFu, best, off);
            if (o > best) best = o;
        }
        if (lid == 0) atomicMax(&g_best[row], best);
    }
}

// Unpack per-row winners; token id < 2^24 is exact in fp32.
__global__ void final_kernel(float* __restrict__ out, int B)
{
    for (int i = threadIdx.x + blockIdx.x * blockDim.x; i < B;
         i += blockDim.x * gridDim.x) {
        unsigned int invIdx = (unsigned int)(g_best[i] & 0xFFFFFFFFull);
        out[i] = (float)(~invIdx);
    }
}

extern "C" void kernel_launch(void* const* d_in, const int* in_sizes, int n_in,
                              void* d_out, int out_size)
{
    // Identify inputs by SIZE, not order:
    //   temperatures -> unique smallest [B]; logits/exp_noise -> the big pair.
    int smallIdx = 0;
    for (int i = 1; i < n_in; i++)
        if (in_sizes[i] < in_sizes[smallIdx]) smallIdx = i;

    int bigIdx0 = -1, bigIdx1 = -1;
    for (int i = 0; i < n_in; i++) {
        if (i == smallIdx) continue;
        if (bigIdx0 < 0) bigIdx0 = i; else bigIdx1 = i;
    }

    const float* temps = (const float*)d_in[smallIdx];
    const float* big0  = (const float*)d_in[bigIdx0];
    const float* big1  = (const float*)d_in[bigIdx1];
    float* out = (float*)d_out;                 // __output__ is float32

    const int B = in_sizes[smallIdx];           // 256
    const int V = in_sizes[bigIdx0] / B;        // 128000

    init_kernel<<<1, 256>>>(big0, B, 1024);
    draft_sampler_kernel<<<B * SEGS, BLOCK>>>(big0, big1, temps, B, V);
    final_kernel<<<1, 256>>>(out, B);
}

// round 10
// speedup vs baseline: 1.3270x; 1.3270x over previous
#include <cuda_runtime.h>
#include <stdint.h>

#define EPS 1e-10f
#define BLOCK 256
#define SEGS 2
#define MAX_B 4096

// Per-(row,segment) winners, packed u64: high 32 = order-preserving key bits,
// low 32 = ~idx (so at equal key, LOWER index wins the max — jnp.argmax tie rule).
__device__ unsigned long long g_seg[MAX_B * SEGS];
// Arrival counters, zero-initialized at module load and RESET by the last CTA
// of each row every launch -> clean across graph replays, no init kernel.
__device__ int g_count[MAX_B];

__device__ __forceinline__ unsigned int order_f32(float f)
{
    unsigned int u = __float_as_uint(f);
    unsigned int m = ((int)u >> 31) | 0x80000000u;  // neg: all ones; pos: sign bit
    return u ^ m;                                    // monotone float -> uint
}

// One kernel does everything.
// Key math: argmax( softmax(l/t) / (n+EPS) ) == argmax( l/t - log(n+EPS) )
// (softmax shift + normalizer are row constants; log is monotone).
// Greedy rows (t==0): argmax(l), noise never read.
__global__ __launch_bounds__(BLOCK, 4) void draft_sampler_kernel(
    const float* __restrict__ big0,
    const float* __restrict__ big1,
    const float* __restrict__ temps,
    float* __restrict__ out,
    int B, int V)
{
    const int row = blockIdx.x >> 1;         // SEGS == 2
    const int seg = blockIdx.x & 1;

    const int nvec = V >> 2;                  // V % 4 == 0 (128000)
    const int segLen = nvec / SEGS;
    const int lo = seg * segLen;
    const int hi = (seg == SEGS - 1) ? nvec : lo + segLen;

    const long long rowBase = (long long)row * V;

    // ---- Per-CTA detection: is big0 logits (has negatives) or exp_noise (>=0)?
    // Warp 0 samples 128 floats from this CTA's own segment (re-read later from
    // cache). logits ~ N(0,1): P(128 samples all >= 0) = 2^-128.
    __shared__ int s_big0_is_logits;
    if (threadIdx.x < 32) {
        const float* p = big0 + rowBase + ((long long)lo << 2);
        bool neg = false;
        #pragma unroll
        for (int k = 0; k < 4; k++)
            neg |= (p[threadIdx.x + 32 * k] < 0.0f);
        unsigned int m = __ballot_sync(0xFFFFFFFFu, neg);
        if (threadIdx.x == 0) s_big0_is_logits = (m != 0u);
    }
    __syncthreads();

    const float* __restrict__ logits = s_big0_is_logits ? big0 : big1;
    const float* __restrict__ noise  = s_big0_is_logits ? big1 : big0;

    const float t = temps[row];
    const bool greedy = (t == 0.0f);
    const float inv_t = greedy ? 1.0f : (1.0f / t);

    const float4* __restrict__ l4 =
        reinterpret_cast<const float4*>(logits + rowBase);
    const float4* __restrict__ n4 =
        reinterpret_cast<const float4*>(noise + rowBase);

    float bestKey = -3.402823466e38f;
    int   bestIdx = 0;

#define TAKE(K, IDX) if ((K) > bestKey) { bestKey = (K); bestIdx = (IDX); }
#define SCAN_L(V4, BI)                \
    TAKE((V4).x, (BI));               \
    TAKE((V4).y, (BI) + 1);           \
    TAKE((V4).z, (BI) + 2);           \
    TAKE((V4).w, (BI) + 3)
#define SCAN_K(LV, NV, BI)                                        \
    TAKE((LV).x * inv_t - __logf((NV).x + EPS), (BI));            \
    TAKE((LV).y * inv_t - __logf((NV).y + EPS), (BI) + 1);        \
    TAKE((LV).z * inv_t - __logf((NV).z + EPS), (BI) + 2);        \
    TAKE((LV).w * inv_t - __logf((NV).w + EPS), (BI) + 3)

    int i = lo + threadIdx.x;
    if (greedy) {
        // 4-deep unroll: 4 independent LDG.128 in flight per thread.
        for (; i + 3 * BLOCK < hi; i += 4 * BLOCK) {
            const float4 a0 = __ldcs(&l4[i]);
            const float4 a1 = __ldcs(&l4[i + BLOCK]);
            const float4 a2 = __ldcs(&l4[i + 2 * BLOCK]);
            const float4 a3 = __ldcs(&l4[i + 3 * BLOCK]);
            SCAN_L(a0, i << 2);
            SCAN_L(a1, (i + BLOCK) << 2);
            SCAN_L(a2, (i + 2 * BLOCK) << 2);
            SCAN_L(a3, (i + 3 * BLOCK) << 2);
        }
        for (; i < hi; i += BLOCK) {
            const float4 a = __ldcs(&l4[i]);
            SCAN_L(a, i << 2);
        }
    } else {
        // 4-deep unroll: 8 independent LDG.128 in flight per thread.
        for (; i + 3 * BLOCK < hi; i += 4 * BLOCK) {
            const float4 a0 = __ldcs(&l4[i]);
            const float4 a1 = __ldcs(&l4[i + BLOCK]);
            const float4 a2 = __ldcs(&l4[i + 2 * BLOCK]);
            const float4 a3 = __ldcs(&l4[i + 3 * BLOCK]);
            const float4 b0 = __ldcs(&n4[i]);
            const float4 b1 = __ldcs(&n4[i + BLOCK]);
            const float4 b2 = __ldcs(&n4[i + 2 * BLOCK]);
            const float4 b3 = __ldcs(&n4[i + 3 * BLOCK]);
            SCAN_K(a0, b0, i << 2);
            SCAN_K(a1, b1, (i + BLOCK) << 2);
            SCAN_K(a2, b2, (i + 2 * BLOCK) << 2);
            SCAN_K(a3, b3, (i + 3 * BLOCK) << 2);
        }
        for (; i < hi; i += BLOCK) {
            const float4 a = __ldcs(&l4[i]);
            const float4 b = __ldcs(&n4[i]);
            SCAN_K(a, b, i << 2);
        }
    }

    // ---- Block reduction on packed u64 (tie-break folded into ~idx).
    unsigned long long best =
        ((unsigned long long)order_f32(bestKey) << 32) | (unsigned int)(~bestIdx);

    #pragma unroll
    for (int off = 16; off > 0; off >>= 1) {
        unsigned long long o = __shfl_down_sync(0xFFFFFFFFu, best, off);
        if (o > best) best = o;
    }

    __shared__ unsigned long long sbest[BLOCK / 32];
    const int wid = threadIdx.x >> 5;
    const int lid = threadIdx.x & 31;
    if (lid == 0) sbest[wid] = best;
    __syncthreads();

    if (threadIdx.x == 0) {
        #pragma unroll
        for (int w = 1; w < BLOCK / 32; w++)
            if (sbest[w] > best) best = sbest[w];

        // Publish segment result, then last-arriving CTA finalizes the row.
        g_seg[row * SEGS + seg] = best;
        __threadfence();
        const int old = atomicAdd(&g_count[row], 1);
        if (old == SEGS - 1) {
            unsigned long long m = g_seg[row * SEGS];
            #pragma unroll
            for (int s = 1; s < SEGS; s++) {
                const unsigned long long v = g_seg[row * SEGS + s];
                if (v > m) m = v;
            }
            // token id < 2^24: exact in fp32
            out[row] = (float)(~(unsigned int)(m & 0xFFFFFFFFull));
            g_count[row] = 0;   // self-clean for the next graph replay
        }
    }
}

extern "C" void kernel_launch(void* const* d_in, const int* in_sizes, int n_in,
                              void* d_out, int out_size)
{
    // Identify inputs by SIZE, not order:
    //   temperatures -> unique smallest [B]; logits/exp_noise -> the big pair
    //   (disambiguated on-device by sign).
    int smallIdx = 0;
    for (int i = 1; i < n_in; i++)
        if (in_sizes[i] < in_sizes[smallIdx]) smallIdx = i;

    int bigIdx0 = -1, bigIdx1 = -1;
    for (int i = 0; i < n_in; i++) {
        if (i == smallIdx) continue;
        if (bigIdx0 < 0) bigIdx0 = i; else bigIdx1 = i;
    }

    const float* temps = (const float*)d_in[smallIdx];
    const float* big0  = (const float*)d_in[bigIdx0];
    const float* big1  = (const float*)d_in[bigIdx1];
    float* out = (float*)d_out;                 // __output__ is float32

    const int B = in_sizes[smallIdx];           // 256
    const int V = in_sizes[bigIdx0] / B;        // 128000

    draft_sampler_kernel<<<B * SEGS, BLOCK>>>(big0, big1, temps, out, B, V);
}